// round 16
// baseline (speedup 1.0000x reference)
#include <cuda_runtime.h>
#include <cuda_bf16.h>
#include <cstdint>

// LightConv: out[b,t,h*S+s] = sum_k softmax_k(filters[b,t,h*K+k]) * x[b, t+k-PAD, h*S+s] + bias[h*S+s]
// B=8 T=1024 H=8 S=64 K=31 C=512

#define B_ 8
#define T_ 1024
#define H_ 8
#define S_ 64
#define K_ 31
#define C_ 512
#define HK_ (H_ * K_)      // 248
#define PAD_ 15            // K/2
#define TTILE 64           // t rows per CTA
#define RT 4               // t rows per thread (x 4 channels)
#define NTHREADS 256       // 16 t-groups x 16 float4 lanes
#define XROWS (TTILE + 2 * PAD_)   // 94
#define XPAD 68            // x row stride in floats (Delta4 rows -> +16 banks; 16B-aligned)
#define WROWF 36           // f32 weight row stride (144 B; Delta4 rows -> +16 banks; 8B chunks aligned)

// xs: 94*68*4 = 25568 B ; wd: 64*36*4 = 9216 B ; total 34784 B
// 6 CTAs/SM: smem 208.7 KB <= 228 KB, regs cap 42 (65536/1536)
#define SMEM_BYTES (XROWS * XPAD * 4 + TTILE * WROWF * 4)

typedef unsigned long long u64;

__device__ __forceinline__ u64 pack2(float w) {
    u64 d;
    asm("mov.b64 %0, {%1, %1};" : "=l"(d) : "f"(w));
    return d;
}
__device__ __forceinline__ u64 pack2f(float a, float b) {
    u64 d;
    asm("mov.b64 %0, {%1, %2};" : "=l"(d) : "f"(a), "f"(b));
    return d;
}
__device__ __forceinline__ void fma2(u64& a, u64 x, u64 w) {
    asm("fma.rn.f32x2 %0, %1, %2, %3;" : "=l"(a) : "l"(x), "l"(w), "l"(a));
}
__device__ __forceinline__ float2 unpack2(u64 v) {
    float2 f;
    asm("mov.b64 {%0, %1}, %2;" : "=f"(f.x), "=f"(f.y) : "l"(v));
    return f;
}
__device__ __forceinline__ void cp_async16(unsigned int smem_addr, const void* gptr, int src_bytes) {
    asm volatile("cp.async.cg.shared.global [%0], [%1], 16, %2;"
                 :: "r"(smem_addr), "l"(gptr), "r"(src_bytes));
}

__global__ __launch_bounds__(NTHREADS, 6) void lightconv_kernel(
    const float* __restrict__ x,
    const float* __restrict__ filters,
    const float* __restrict__ bias,
    float* __restrict__ out)
{
    extern __shared__ float smem[];
    float* xs = smem;                      // [XROWS][XPAD]
    float* wd = smem + XROWS * XPAD;       // t-major: [TTILE][WROWF]

    const int t0   = blockIdx.x * TTILE;
    const int h    = blockIdx.y;
    const int b    = blockIdx.z;
    const int tid  = threadIdx.x;
    const int lane = tid & 31;
    const int warp = tid >> 5;

    // ---- async x tile load (overlapped with softmax below) ----
    const float4* xbase4 = reinterpret_cast<const float4*>(x + (size_t)b * T_ * C_ + h * S_);
    #pragma unroll 3
    for (int idx = tid; idx < XROWS * 16; idx += NTHREADS) {
        int row  = idx >> 4;
        int col4 = idx & 15;
        int t    = t0 + row - PAD_;
        bool ok  = (t >= 0) && (t < T_);
        int tc   = ok ? t : 0;   // clamped valid address; src-size 0 does the zero-fill
        const float4* src = xbase4 + (size_t)tc * (C_ / 4) + col4;
        unsigned int dst =
            (unsigned int)__cvta_generic_to_shared(xs + row * XPAD + col4 * 4);
        cp_async16(dst, src, ok ? 16 : 0);
    }
    asm volatile("cp.async.commit_group;" ::: "memory");

    // ---- softmax over K=31 taps (runs while x streams in) ----
    // warp per t-row, lane = k; 2 rows/iter; store f32 t-major
    const float* fbase = filters + (size_t)b * T_ * HK_ + h * K_;
    #pragma unroll
    for (int row = warp; row < TTILE; row += 16) {
        int rowB = row + 8;
        float fA = -1e30f, fB = -1e30f;
        if (lane < K_) {
            fA = fbase[(size_t)(t0 + row)  * HK_ + lane];
            fB = fbase[(size_t)(t0 + rowB) * HK_ + lane];
        }
        float mA = fA, mB = fB;
        #pragma unroll
        for (int o = 16; o > 0; o >>= 1) {
            mA = fmaxf(mA, __shfl_xor_sync(0xffffffffu, mA, o));
            mB = fmaxf(mB, __shfl_xor_sync(0xffffffffu, mB, o));
        }
        float eA = (lane < K_) ? __expf(fA - mA) : 0.0f;
        float eB = (lane < K_) ? __expf(fB - mB) : 0.0f;
        float sA = eA, sB = eB;
        #pragma unroll
        for (int o = 16; o > 0; o >>= 1) {
            sA += __shfl_xor_sync(0xffffffffu, sA, o);
            sB += __shfl_xor_sync(0xffffffffu, sB, o);
        }
        if (lane < K_) {
            wd[row  * WROWF + lane] = eA * (1.0f / sA);
            wd[rowB * WROWF + lane] = eB * (1.0f / sB);
        }
    }
    asm volatile("cp.async.wait_group 0;" ::: "memory");
    __syncthreads();

    // ---- main product ----
    // thread = (s4: 4 channels as 2x f32x2) x (tg: RT=4 t rows)
    // warp halves = t-groups tg, tg+1 (Delta=4 rows): x rows +16 banks,
    // w rows +16 banks -> all LDS conflict-free.
    const int s4 = tid & 15;
    const int tg = tid >> 4;       // 0..15
    const int tl = tg * RT;

    const ulonglong2* xs2 = reinterpret_cast<const ulonglong2*>(xs) + s4;  // + row*(XPAD/4)
    const float* wrow = wd + tl * WROWF;

    // init accumulators with bias
    float4 bv = reinterpret_cast<const float4*>(bias + h * S_)[s4];
    u64 acc[RT][2];
    #pragma unroll
    for (int r = 0; r < RT; ++r) {
        acc[r][0] = pack2f(bv.x, bv.y);
        acc[r][1] = pack2f(bv.z, bv.w);
    }

    // Region 1: j = 0..3 triangular (scalar weight loads, static guards)
    #pragma unroll
    for (int j = 0; j < RT; ++j) {
        ulonglong2 xv = xs2[(tl + j) * (XPAD / 4)];
        #pragma unroll
        for (int r = 0; r < RT; ++r) {
            if (r <= j) {
                u64 w2 = pack2(wrow[r * WROWF + (j - r)]);
                fma2(acc[r][0], xv.x, w2);
                fma2(acc[r][1], xv.y, w2);
            }
        }
    }

    // Period-2 f32 register weight cache: wreg[r][0..1] = 2 consecutive taps.
    // Preload chunks current at entry j=4: r=1 -> taps{2,3}, r=3 -> taps{0,1}
    // (r=0 and r=2 reload at j=4 itself).
    float wreg[RT][2];
    *reinterpret_cast<float2*>(wreg[1]) =
        *reinterpret_cast<const float2*>(wrow + 1 * WROWF + 2);
    *reinterpret_cast<float2*>(wreg[3]) =
        *reinterpret_cast<const float2*>(wrow + 3 * WROWF + 0);

    // Region 2: steady state j = 4..30 (uniform, fully unrolled).
    // Per j: reload wreg[r] for r in {j&1, (j&1)+2}, chunk base (j-r) [even, 8B-aligned].
    #pragma unroll
    for (int j = RT; j <= 30; ++j) {
        const int r0 = j & 1;
        const int r1 = r0 + 2;
        *reinterpret_cast<float2*>(wreg[r0]) =
            *reinterpret_cast<const float2*>(wrow + r0 * WROWF + (j - r0));
        *reinterpret_cast<float2*>(wreg[r1]) =
            *reinterpret_cast<const float2*>(wrow + r1 * WROWF + (j - r1));
        ulonglong2 xv = xs2[(tl + j) * (XPAD / 4)];
        #pragma unroll
        for (int r = 0; r < RT; ++r) {
            u64 w2 = pack2(wreg[r][(j - r) & 1]);
            fma2(acc[r][0], xv.x, w2);
            fma2(acc[r][1], xv.y, w2);
        }
    }

    // Region 3: j = 31..33 triangular (scalar weight loads, static guards)
    #pragma unroll
    for (int j = K_; j < K_ + RT - 1; ++j) {
        ulonglong2 xv = xs2[(tl + j) * (XPAD / 4)];
        #pragma unroll
        for (int r = 0; r < RT; ++r) {
            if (j - r < K_) {
                u64 w2 = pack2(wrow[r * WROWF + (j - r)]);
                fma2(acc[r][0], xv.x, w2);
                fma2(acc[r][1], xv.y, w2);
            }
        }
    }

    // ---- epilogue: vectorized store (bias already folded in) ----
    float4* outbase = reinterpret_cast<float4*>(
        out + ((size_t)b * T_ + t0 + tl) * C_ + h * S_) + s4;
    #pragma unroll
    for (int r = 0; r < RT; ++r) {
        float2 lo = unpack2(acc[r][0]);
        float2 hi = unpack2(acc[r][1]);
        float4 o;
        o.x = lo.x;
        o.y = lo.y;
        o.z = hi.x;
        o.w = hi.y;
        outbase[(size_t)r * (C_ / 4)] = o;
    }
}

extern "C" void kernel_launch(void* const* d_in, const int* in_sizes, int n_in,
                              void* d_out, int out_size)
{
    const float* x       = (const float*)d_in[0];
    const float* filters = (const float*)d_in[1];
    const float* bias    = (const float*)d_in[2];
    float* out           = (float*)d_out;

    cudaFuncSetAttribute(lightconv_kernel,
                         cudaFuncAttributeMaxDynamicSharedMemorySize, SMEM_BYTES);

    dim3 grid(T_ / TTILE, H_, B_);   // (16, 8, 8) = 1024 CTAs, 6 CTAs/SM target
    lightconv_kernel<<<grid, NTHREADS, SMEM_BYTES>>>(x, filters, bias, out);
}